// round 5
// baseline (speedup 1.0000x reference)
#include <cuda_runtime.h>

// Parametric LIF forward — R5: R1 shape (float4/thread, 1024x128) with
// evict-first streaming loads (__ldcs) as the ONLY isolated change.
// Rationale: reads are touch-once; keeping them out of L2 preserves
// capacity for dirty output lines -> longer write-drain runs at DRAM.
//
// x: [B=64, T=64, N=8192] fp32. Per channel (b,n), sequential over t:
//   u    = last * sig + x[t]
//   s    = (u >= th) ? 1 : 0
//   last = s ? 0 : u + lamb*(u - last)
//   out[t] = s

#ifndef LIF_B
#define LIF_B 64
#define LIF_T 64
#define LIF_N 8192
#endif

__global__ __launch_bounds__(128) void lif_fwd_kernel(
    const float* __restrict__ x,
    const float* __restrict__ tau_p,
    const float* __restrict__ lamb_p,
    const float* __restrict__ th_p,
    float* __restrict__ out)
{
    constexpr int NV = LIF_N / 4;              // 2048 float4 groups per row
    const int idx = blockIdx.x * blockDim.x + threadIdx.x;
    const int b  = idx >> 11;                  // idx / 2048
    const int nv = idx & (NV - 1);             // idx % 2048

    const float tp   = tau_p[0];
    const float sig  = 1.0f / (1.0f + __expf(-tp));
    const float lamb = lamb_p[0];
    const float th   = th_p[0];

    const float4* __restrict__ xp = reinterpret_cast<const float4*>(x)
                                    + (size_t)b * LIF_T * NV + nv;
    float4* __restrict__ op = reinterpret_cast<float4*>(out)
                              + (size_t)b * LIF_T * NV + nv;

    float l0 = 0.f, l1 = 0.f, l2 = 0.f, l3 = 0.f;

    #pragma unroll 16
    for (int t = 0; t < LIF_T; ++t) {
        const float4 xv = __ldcs(&xp[(size_t)t * NV]);   // streaming, evict-first

        float u0 = fmaf(l0, sig, xv.x);
        float s0 = (u0 >= th) ? 1.0f : 0.0f;
        l0 = (u0 >= th) ? 0.0f : fmaf(lamb, u0 - l0, u0);

        float u1 = fmaf(l1, sig, xv.y);
        float s1 = (u1 >= th) ? 1.0f : 0.0f;
        l1 = (u1 >= th) ? 0.0f : fmaf(lamb, u1 - l1, u1);

        float u2 = fmaf(l2, sig, xv.z);
        float s2 = (u2 >= th) ? 1.0f : 0.0f;
        l2 = (u2 >= th) ? 0.0f : fmaf(lamb, u2 - l2, u2);

        float u3 = fmaf(l3, sig, xv.w);
        float s3 = (u3 >= th) ? 1.0f : 0.0f;
        l3 = (u3 >= th) ? 0.0f : fmaf(lamb, u3 - l3, u3);

        float4 sv;
        sv.x = s0; sv.y = s1; sv.z = s2; sv.w = s3;
        op[(size_t)t * NV] = sv;
    }
}

extern "C" void kernel_launch(void* const* d_in, const int* in_sizes, int n_in,
                              void* d_out, int out_size)
{
    const float* x    = (const float*)d_in[0];
    const float* tau  = (const float*)d_in[1];
    const float* lamb = (const float*)d_in[2];
    const float* th   = (const float*)d_in[3];
    float* out = (float*)d_out;

    constexpr int NV = LIF_N / 4;
    constexpr int total = LIF_B * NV;          // 131072 threads
    constexpr int block = 128;
    lif_fwd_kernel<<<total / block, block>>>(x, tau, lamb, th, out);
}

// round 6
// speedup vs baseline: 1.2573x; 1.2573x over previous
#include <cuda_runtime.h>

// Parametric LIF forward — R6: exact R1 compute (float4/thread, plain LDG/STG,
// no cache hints — R5 proved __ldcs costs 11us). Single isolated change vs R1:
// block 128 -> 256 at the same 131072 total threads (512 blocks), to halve
// CTA-boundary count. Everything else byte-identical to the 38.5us best.
//
// x: [B=64, T=64, N=8192] fp32. Per channel (b,n), sequential over t:
//   u    = last * sig + x[t]
//   s    = (u >= th) ? 1 : 0
//   last = s ? 0 : u + lamb*(u - last)
//   out[t] = s

#ifndef LIF_B
#define LIF_B 64
#define LIF_T 64
#define LIF_N 8192
#endif

__global__ __launch_bounds__(256) void lif_fwd_kernel(
    const float* __restrict__ x,
    const float* __restrict__ tau_p,
    const float* __restrict__ lamb_p,
    const float* __restrict__ th_p,
    float* __restrict__ out)
{
    constexpr int NV = LIF_N / 4;              // 2048 float4 groups per row
    const int idx = blockIdx.x * blockDim.x + threadIdx.x;
    const int b  = idx >> 11;                  // idx / 2048
    const int nv = idx & (NV - 1);             // idx % 2048

    const float tp   = tau_p[0];
    const float sig  = 1.0f / (1.0f + __expf(-tp));
    const float lamb = lamb_p[0];
    const float th   = th_p[0];

    const float4* __restrict__ xp = reinterpret_cast<const float4*>(x)
                                    + (size_t)b * LIF_T * NV + nv;
    float4* __restrict__ op = reinterpret_cast<float4*>(out)
                              + (size_t)b * LIF_T * NV + nv;

    float l0 = 0.f, l1 = 0.f, l2 = 0.f, l3 = 0.f;

    #pragma unroll 16
    for (int t = 0; t < LIF_T; ++t) {
        const float4 xv = xp[(size_t)t * NV];

        float u0 = fmaf(l0, sig, xv.x);
        float s0 = (u0 >= th) ? 1.0f : 0.0f;
        l0 = (u0 >= th) ? 0.0f : fmaf(lamb, u0 - l0, u0);

        float u1 = fmaf(l1, sig, xv.y);
        float s1 = (u1 >= th) ? 1.0f : 0.0f;
        l1 = (u1 >= th) ? 0.0f : fmaf(lamb, u1 - l1, u1);

        float u2 = fmaf(l2, sig, xv.z);
        float s2 = (u2 >= th) ? 1.0f : 0.0f;
        l2 = (u2 >= th) ? 0.0f : fmaf(lamb, u2 - l2, u2);

        float u3 = fmaf(l3, sig, xv.w);
        float s3 = (u3 >= th) ? 1.0f : 0.0f;
        l3 = (u3 >= th) ? 0.0f : fmaf(lamb, u3 - l3, u3);

        float4 sv;
        sv.x = s0; sv.y = s1; sv.z = s2; sv.w = s3;
        op[(size_t)t * NV] = sv;
    }
}

extern "C" void kernel_launch(void* const* d_in, const int* in_sizes, int n_in,
                              void* d_out, int out_size)
{
    const float* x    = (const float*)d_in[0];
    const float* tau  = (const float*)d_in[1];
    const float* lamb = (const float*)d_in[2];
    const float* th   = (const float*)d_in[3];
    float* out = (float*)d_out;

    constexpr int NV = LIF_N / 4;
    constexpr int total = LIF_B * NV;          // 131072 threads
    constexpr int block = 256;
    lif_fwd_kernel<<<total / block, block>>>(x, tau, lamb, th, out);
}